// round 2
// baseline (speedup 1.0000x reference)
#include <cuda_runtime.h>
#include <math.h>

// Problem constants
#define T_DIM   36
#define NPOLES  40
#define KDIM    160          // 4*N_POLES
#define PDIM    4096
#define BDIM    2
#define PCOLS   64           // columns per CTA
#define NCTA    128          // 8192 columns / 64
#define NTHREADS 256         // 8 warps -> 2 per SMSP, balanced
#define MAXIT   100
#define LAM_C   0.1f
#define TOL_C   1e-4f

// ---------------- device globals (no allocation allowed) ----------------
__device__ float    g_Dmat[T_DIM * KDIM];   // normalized dictionary, [t][k]
__device__ float    g_A[KDIM * KDIM];       // I - DtD/L (symmetric)
__device__ float    g_lambd;
__device__ float    g_linv;
__device__ float    g_tts[MAXIT];
__device__ float    g_part[NCTA];           // per-CTA ||dx||^2 partials
__device__ unsigned g_count;                // grid barrier counter
__device__ unsigned g_gen;                  // grid barrier generation

// ---------------- packed f32x2 helpers (Blackwell FFMA2) ----------------
typedef unsigned long long ull;

__device__ __forceinline__ ull splat2(float v) {
    ull r;
    asm("mov.b64 %0, {%1, %1};" : "=l"(r) : "f"(v));
    return r;
}
__device__ __forceinline__ void fma2(ull& d, ull a, ull b) {
    asm("fma.rn.f32x2 %0, %1, %2, %0;" : "+l"(d) : "l"(a), "l"(b));
}
__device__ __forceinline__ float2 unpack2(ull v) {
    float2 f;
    asm("mov.b64 {%0, %1}, %2;" : "=f"(f.x), "=f"(f.y) : "l"(v));
    return f;
}

// ---------------- setup: dictionary, DtD, L, A, tts, barrier reset ------
__global__ void setup_kernel(const float* __restrict__ Drr,
                             const float* __restrict__ Dtheta) {
    __shared__ float rbuf[256];
    __shared__ float s_linv;
    const int tid = threadIdx.x;

    // 1. Build normalized dictionary columns (one thread per column)
    if (tid < KDIM) {
        const int j = tid;
        const int g = j / NPOLES;    // 0: rr^i cos, 1: (-rr)^i cos, 2: rr^i sin, 3: (-rr)^i sin
        const int n = j % NPOLES;
        const float rr = Drr[n];
        const float th = Dtheta[n];
        float vals[T_DIM];
        float pr = 1.0f;
        float n2 = 0.0f;
        for (int i = 0; i < T_DIM; ++i) {
            float ang  = (float)i * th;
            float base = (g < 2) ? cosf(ang) : sinf(ang);
            float v = pr * base;
            if ((g & 1) && (i & 1)) v = -v;   // (-1)^i factor
            vals[i] = v;
            n2 += v * v;
            pr *= rr;
        }
        float G  = (n2 == 0.0f) ? 6.0f : sqrtf(n2);  // sqrt(T)=6 fallback
        float gi = 1.0f / G;
        for (int i = 0; i < T_DIM; ++i) g_Dmat[i * KDIM + j] = vals[i] * gi;
    }
    __syncthreads();

    // 2. DtD (stored temporarily in g_A) + Frobenius norm
    float sq = 0.0f;
    for (int e = tid; e < KDIM * KDIM; e += 256) {
        int i = e / KDIM, jj = e % KDIM;
        float s = 0.0f;
        for (int t = 0; t < T_DIM; ++t)
            s += g_Dmat[t * KDIM + i] * g_Dmat[t * KDIM + jj];
        g_A[e] = s;
        sq += s * s;
    }
    rbuf[tid] = sq;
    __syncthreads();
    if (tid == 0) {
        float tot = 0.0f;
        for (int i = 0; i < 256; ++i) tot += rbuf[i];
        float L = sqrtf(tot);
        s_linv  = 1.0f / L;
        g_linv  = s_linv;
        g_lambd = LAM_C * s_linv;
        // FISTA momentum coefficients (double, then cast — matches reference)
        double t = 1.0;
        for (int k = 0; k < MAXIT; ++k) {
            double tn = (1.0 + sqrt(1.0 + 4.0 * t * t)) * 0.5;
            g_tts[k] = (float)((t - 1.0) / tn);
            t = tn;
        }
        g_count = 0;
        g_gen   = 0;
    }
    __syncthreads();

    // 3. A = I - DtD * linv
    const float linv = s_linv;
    for (int e = tid; e < KDIM * KDIM; e += 256) {
        int i = e / KDIM, jj = e % KDIM;
        g_A[e] = ((i == jj) ? 1.0f : 0.0f) - g_A[e] * linv;
    }
    if (tid < NCTA) g_part[tid] = 0.0f;
}

// ---------------- persistent FISTA kernel ------------------------------
// Thread tile: 5 rows (K) x 8 cols (P). 32 row-groups x 8 col-groups = 256 threads.
__global__ void __launch_bounds__(NTHREADS, 1)
fista_kernel(const float* __restrict__ x_in, float* __restrict__ out) {
    extern __shared__ float smem[];
    float* As = smem;                         // 160*160
    float* Ys = As + KDIM * KDIM;             // 160*64  (y; also stages D)
    float* Xs = Ys + KDIM * PCOLS;            // 160*64  (x_old; also stages x tile)
    float* Dt = Xs + KDIM * PCOLS;            // 160*64  (DtY * linv)
    __shared__ float red[NTHREADS];
    __shared__ int   s_stop;

    const int tid   = threadIdx.x;
    const int kr    = tid >> 3;               // 0..31  row group
    const int pc    = tid & 7;                // 0..7   col group
    const int kbase = kr * 5;
    const int pbase = pc * 8;
    const int cta   = blockIdx.x;
    const int b     = cta >> 6;               // batch (64 CTAs per batch)
    const int p0    = (cta & 63) * PCOLS;

    // Load A into shared
    for (int i = tid; i < KDIM * KDIM; i += NTHREADS) As[i] = g_A[i];
    // Stage x tile [36 x 64] into Xs (coalesced)
    for (int i = tid; i < T_DIM * PCOLS; i += NTHREADS) {
        int t = i >> 6, pp = i & 63;
        Xs[i] = x_in[(b * T_DIM + t) * PDIM + p0 + pp];
    }
    // Stage dictionary [36 x 160] into Ys
    for (int i = tid; i < T_DIM * KDIM; i += NTHREADS) Ys[i] = g_Dmat[i];
    __syncthreads();

    const float linv  = g_linv;
    const float lambd = g_lambd;

    // ---- DtY = linv * D^T x  -> Dt (5x8 tile per thread) ----
    {
        float acc[40];
        #pragma unroll
        for (int i = 0; i < 40; ++i) acc[i] = 0.0f;
        #pragma unroll 4
        for (int t = 0; t < T_DIM; ++t) {
            const float* Drow = Ys + t * KDIM + kbase;
            float av[5];
            #pragma unroll
            for (int i = 0; i < 5; ++i) av[i] = Drow[i];
            float4 y0 = *(const float4*)(Xs + t * PCOLS + pbase);
            float4 y1 = *(const float4*)(Xs + t * PCOLS + pbase + 4);
            float yv[8] = {y0.x, y0.y, y0.z, y0.w, y1.x, y1.y, y1.z, y1.w};
            #pragma unroll
            for (int i = 0; i < 5; ++i)
                #pragma unroll
                for (int c = 0; c < 8; ++c)
                    acc[i * 8 + c] = fmaf(av[i], yv[c], acc[i * 8 + c]);
        }
        __syncthreads();
        #pragma unroll
        for (int i = 0; i < 5; ++i)
            #pragma unroll
            for (int c = 0; c < 8; ++c)
                Dt[(kbase + i) * PCOLS + pbase + c] = acc[i * 8 + c] * linv;
    }
    // x0 = 0, y0 = 0
    for (int i = tid; i < KDIM * PCOLS; i += NTHREADS) { Xs[i] = 0.0f; Ys[i] = 0.0f; }
    __syncthreads();

    // ---- main FISTA loop ----
    unsigned genl = 0;
    for (int it = 0; it < MAXIT; ++it) {
        // acc = DtY (packed f32x2), then acc += A @ y
        ull acc2[20];
        #pragma unroll
        for (int i = 0; i < 5; ++i)
            #pragma unroll
            for (int c = 0; c < 4; ++c)
                acc2[i * 4 + c] = *(const ull*)(Dt + (kbase + i) * PCOLS + pbase + 2 * c);

        // A @ y : per j, 5 scalar A loads + 2 LDS.128 of y + 20 FFMA2
        #pragma unroll 4
        for (int j = 0; j < KDIM; ++j) {
            const float* Arow = As + j * KDIM + kbase;
            float a0 = Arow[0], a1 = Arow[1], a2 = Arow[2], a3 = Arow[3], a4 = Arow[4];
            ulonglong2 ya = *(const ulonglong2*)(Ys + j * PCOLS + pbase);
            ulonglong2 yb = *(const ulonglong2*)(Ys + j * PCOLS + pbase + 4);
            ull y2[4] = {ya.x, ya.y, yb.x, yb.y};
            ull s0 = splat2(a0), s1 = splat2(a1), s2 = splat2(a2),
                s3 = splat2(a3), s4 = splat2(a4);
            #pragma unroll
            for (int c = 0; c < 4; ++c) {
                fma2(acc2[0 * 4 + c], s0, y2[c]);
                fma2(acc2[1 * 4 + c], s1, y2[c]);
                fma2(acc2[2 * 4 + c], s2, y2[c]);
                fma2(acc2[3 * 4 + c], s3, y2[c]);
                fma2(acc2[4 * 4 + c], s4, y2[c]);
            }
        }

        const float tt = g_tts[it];
        float dsum = 0.0f;
        __syncthreads();   // all reads of Ys complete before overwrite

        // shrink + momentum + local ||dx||^2
        #pragma unroll
        for (int i = 0; i < 5; ++i) {
            #pragma unroll
            for (int c = 0; c < 4; ++c) {
                float2 v2 = unpack2(acc2[i * 4 + c]);
                int idx = (kbase + i) * PCOLS + pbase + 2 * c;
                {
                    float v  = v2.x;
                    float a  = fabsf(v) - lambd;
                    float xn = (a > 0.0f) ? copysignf(a, v) : 0.0f;
                    float xo = Xs[idx];
                    float d  = xn - xo;
                    dsum += d * d;
                    Ys[idx] = xn * (1.0f + tt) - xo * tt;
                    Xs[idx] = xn;
                }
                {
                    float v  = v2.y;
                    float a  = fabsf(v) - lambd;
                    float xn = (a > 0.0f) ? copysignf(a, v) : 0.0f;
                    float xo = Xs[idx + 1];
                    float d  = xn - xo;
                    dsum += d * d;
                    Ys[idx + 1] = xn * (1.0f + tt) - xo * tt;
                    Xs[idx + 1] = xn;
                }
            }
        }

        // block-reduce dsum (fixed order -> deterministic)
        red[tid] = dsum;
        __syncthreads();
        if (tid == 0) {
            float s = 0.0f;
            for (int i = 0; i < NTHREADS; ++i) s += red[i];
            g_part[cta] = s;
        }

        // ---- software grid barrier ----
        __syncthreads();
        if (tid == 0) {
            __threadfence();
            unsigned tk = atomicAdd(&g_count, 1);
            if (tk == (unsigned)(gridDim.x - 1)) {
                g_count = 0;
                __threadfence();
                atomicAdd(&g_gen, 1);
            } else {
                while (*((volatile unsigned*)&g_gen) == genl) { __nanosleep(64); }
            }
            __threadfence();
        }
        __syncthreads();
        genl++;

        // global convergence decision (identical order in every CTA)
        if (tid < NCTA) red[tid] = *((volatile float*)(g_part + tid));
        __syncthreads();
        if (tid == 0) {
            float tot = 0.0f;
            for (int i = 0; i < NCTA; ++i) tot += red[i];
            float denom = (it == 0) ? (float)PDIM : (float)KDIM;
            s_stop = (sqrtf(tot) < TOL_C * denom) ? 1 : 0;
        }
        __syncthreads();
        if (s_stop) break;
    }

    // write output [B, 160, 4096]
    __syncthreads();
    for (int i = tid; i < KDIM * PCOLS; i += NTHREADS) {
        int k = i >> 6, pp = i & 63;
        out[(b * KDIM + k) * PDIM + p0 + pp] = Xs[i];
    }
}

// ---------------- launch ------------------------------------------------
extern "C" void kernel_launch(void* const* d_in, const int* in_sizes, int n_in,
                              void* d_out, int out_size) {
    const float* Drr    = (const float*)d_in[0];
    const float* Dtheta = (const float*)d_in[1];
    const float* x      = (const float*)d_in[2];
    float* out = (float*)d_out;

    const size_t smem = (size_t)(KDIM * KDIM + 3 * KDIM * PCOLS) * sizeof(float); // 225,280 B
    cudaFuncSetAttribute(fista_kernel, cudaFuncAttributeMaxDynamicSharedMemorySize, (int)smem);

    setup_kernel<<<1, 256>>>(Drr, Dtheta);
    fista_kernel<<<NCTA, NTHREADS, smem>>>(x, out);
}

// round 4
// speedup vs baseline: 3.7559x; 3.7559x over previous
#include <cuda_runtime.h>
#include <cuda_bf16.h>
#include <math.h>
#include <stdint.h>

// Problem constants
#define T_DIM   36
#define NPOLES  40
#define KDIM    160          // 4*N_POLES
#define PDIM    4096
#define PCOLS   64           // p columns per CTA
#define NCTA    128
#define NTHREADS 256         // 8 warps: 2 (m) x 4 (n)
#define MAXIT   100
#define LAM_C   0.1f
#define TOL_C   1e-4f

#define YSTR    164          // y fp32 row stride (floats)

// ---- dynamic smem layout (bytes) ----
#define RED_OFF   0          // 256 floats
#define STOP_OFF  1024
#define A_HI_OFF  2048       // 100 frags * 32 lanes * 16B = 51200
#define A_LO_OFF  53248      // 51200
#define DTY_OFF   104448     // 80 c-frags * 32 * 16B = 40960
#define Y_OFF     145408     // 64 * 164 * 4 = 41984
#define SMEM_TOTAL 187392
// startup staging (consumed before overwrite):
#define DICT_STAGE Y_OFF     // dict [36][160] fp32 = 23040
#define X_STAGE    DTY_OFF   // x tile [36][64] fp32 = 9216

// ---------------- device globals ----------------
__device__ float    g_Dmat[T_DIM * KDIM];   // [t][k]
__device__ float    g_A[KDIM * KDIM];       // I - DtD/L  [k][j]
__device__ float    g_lambd;
__device__ float    g_linv;
__device__ float    g_tts[MAXIT];
__device__ float    g_part[NCTA];
__device__ unsigned g_count;
__device__ unsigned g_gen;

// ---------------- helpers ----------------
__device__ __forceinline__ void mma_bf16(float* c, const uint32_t* a, const uint32_t* b) {
    asm volatile(
        "mma.sync.aligned.m16n8k16.row.col.f32.bf16.bf16.f32 "
        "{%0,%1,%2,%3}, {%4,%5,%6,%7}, {%8,%9}, {%0,%1,%2,%3};"
        : "+f"(c[0]), "+f"(c[1]), "+f"(c[2]), "+f"(c[3])
        : "r"(a[0]), "r"(a[1]), "r"(a[2]), "r"(a[3]), "r"(b[0]), "r"(b[1]));
}
__device__ __forceinline__ void split_pack(float v0, float v1, uint32_t& hi, uint32_t& lo) {
    asm("cvt.rn.bf16x2.f32 %0, %1, %2;" : "=r"(hi) : "f"(v1), "f"(v0));
    float h0 = __uint_as_float(hi << 16);
    float h1 = __uint_as_float(hi & 0xffff0000u);
    asm("cvt.rn.bf16x2.f32 %0, %1, %2;" : "=r"(lo) : "f"(v1 - h1), "f"(v0 - h0));
}

// ---------------- setup ----------------
__global__ void setup_kernel(const float* __restrict__ Drr,
                             const float* __restrict__ Dtheta) {
    __shared__ float rbuf[256];
    __shared__ float s_linv;
    const int tid = threadIdx.x;

    if (tid < KDIM) {
        const int j = tid;
        const int g = j / NPOLES;
        const int n = j % NPOLES;
        const float rr = Drr[n];
        const float th = Dtheta[n];
        float vals[T_DIM];
        float pr = 1.0f, n2 = 0.0f;
        for (int i = 0; i < T_DIM; ++i) {
            float ang  = (float)i * th;
            float base = (g < 2) ? cosf(ang) : sinf(ang);
            float v = pr * base;
            if ((g & 1) && (i & 1)) v = -v;
            vals[i] = v; n2 += v * v; pr *= rr;
        }
        float G  = (n2 == 0.0f) ? 6.0f : sqrtf(n2);
        float gi = 1.0f / G;
        for (int i = 0; i < T_DIM; ++i) g_Dmat[i * KDIM + j] = vals[i] * gi;
    }
    __syncthreads();

    float sq = 0.0f;
    for (int e = tid; e < KDIM * KDIM; e += 256) {
        int i = e / KDIM, jj = e % KDIM;
        float s = 0.0f;
        for (int t = 0; t < T_DIM; ++t)
            s += g_Dmat[t * KDIM + i] * g_Dmat[t * KDIM + jj];
        g_A[e] = s;
        sq += s * s;
    }
    rbuf[tid] = sq;
    __syncthreads();
    if (tid == 0) {
        float tot = 0.0f;
        for (int i = 0; i < 256; ++i) tot += rbuf[i];
        float L = sqrtf(tot);
        s_linv  = 1.0f / L;
        g_linv  = s_linv;
        g_lambd = LAM_C * s_linv;
        double t = 1.0;
        for (int k = 0; k < MAXIT; ++k) {
            double tn = (1.0 + sqrt(1.0 + 4.0 * t * t)) * 0.5;
            g_tts[k] = (float)((t - 1.0) / tn);
            t = tn;
        }
        g_count = 0;
        g_gen   = 0;
    }
    __syncthreads();
    const float linv = s_linv;
    for (int e = tid; e < KDIM * KDIM; e += 256) {
        int i = e / KDIM, jj = e % KDIM;
        g_A[e] = ((i == jj) ? 1.0f : 0.0f) - g_A[e] * linv;
    }
    if (tid < NCTA) g_part[tid] = 0.0f;
}

// ---------------- persistent FISTA kernel (mma.sync bf16) ----------------
__global__ void __launch_bounds__(NTHREADS, 1)
fista_kernel(const float* __restrict__ x_in, float* __restrict__ out) {
    extern __shared__ __align__(16) char smem[];
    float* red    = (float*)(smem + RED_OFF);
    int*   s_stop = (int*)(smem + STOP_OFF);

    const int tid = threadIdx.x;
    const int wid = tid >> 5;
    const int l   = tid & 31;
    const int wm  = wid >> 2;          // 0..1  (80-row half)
    const int wn  = wid & 3;           // 0..3  (16-col stripe)
    const int g   = l >> 2;            // groupID
    const int i4  = l & 3;             // threadID_in_group
    const int cta = blockIdx.x;
    const int b   = cta >> 6;
    const int p0  = (cta & 63) * PCOLS;

    const float linv  = g_linv;
    const float lambd = g_lambd;

    // ---- stage dict [36][160] and x tile [36][64] fp32 ----
    for (int e = tid; e < T_DIM * KDIM; e += NTHREADS)
        *(float*)(smem + DICT_STAGE + e * 4) = g_Dmat[e];
    for (int e = tid; e < T_DIM * PCOLS; e += NTHREADS) {
        int t = e >> 6, pp = e & 63;
        *(float*)(smem + X_STAGE + e * 4) = x_in[(b * T_DIM + t) * PDIM + p0 + pp];
    }
    __syncthreads();

    // ---- DtY = linv * D^T x -> registers (c-frag order per thread) ----
    // thread positions: mt 0..4, nt 0..1, q 0..3
    //   row = wm*80 + mt*16 + g + (q>>1)*8 ; col = wn*16 + nt*8 + i4*2 + (q&1)
    float dty[40];
    {
        #pragma unroll
        for (int v = 0; v < 40; ++v) dty[v] = 0.0f;
        const float* Ds = (const float*)(smem + DICT_STAGE);
        const float* Xs = (const float*)(smem + X_STAGE);
        for (int t = 0; t < T_DIM; ++t) {
            float dr[10], xc[4];
            #pragma unroll
            for (int mt = 0; mt < 5; ++mt) {
                dr[mt * 2]     = Ds[t * KDIM + wm * 80 + mt * 16 + g];
                dr[mt * 2 + 1] = Ds[t * KDIM + wm * 80 + mt * 16 + g + 8];
            }
            #pragma unroll
            for (int nt = 0; nt < 2; ++nt) {
                xc[nt * 2]     = Xs[t * PCOLS + wn * 16 + nt * 8 + i4 * 2];
                xc[nt * 2 + 1] = Xs[t * PCOLS + wn * 16 + nt * 8 + i4 * 2 + 1];
            }
            #pragma unroll
            for (int mt = 0; mt < 5; ++mt)
                #pragma unroll
                for (int nt = 0; nt < 2; ++nt)
                    #pragma unroll
                    for (int q = 0; q < 4; ++q)
                        dty[(mt * 2 + nt) * 4 + q] =
                            fmaf(dr[mt * 2 + (q >> 1)], xc[nt * 2 + (q & 1)],
                                 dty[(mt * 2 + nt) * 4 + q]);
        }
        #pragma unroll
        for (int v = 0; v < 40; ++v) dty[v] *= linv;
    }
    __syncthreads();   // dict/x staging consumed

    // ---- pack A into fragment-native bf16 hi/lo layout ----
    // frag = mtileG*10 + kstep ; entry addr = (frag*32 + lane)*16 + reg*4
    for (int e = tid; e < 100 * 32 * 4; e += NTHREADS) {
        int frag = e >> 7;
        int lane = (e >> 2) & 31;
        int reg  = e & 3;
        int mt   = frag / 10, ks = frag % 10;
        int r = mt * 16 + (lane >> 2) + ((reg & 1) ? 8 : 0);
        int k = ks * 16 + (lane & 3) * 2 + ((reg & 2) ? 8 : 0);
        float v0 = g_A[r * KDIM + k];
        float v1 = g_A[r * KDIM + k + 1];
        uint32_t hi, lo;
        split_pack(v0, v1, hi, lo);
        *(uint32_t*)(smem + A_HI_OFF + e * 4) = hi;
        *(uint32_t*)(smem + A_LO_OFF + e * 4) = lo;
    }
    // ---- store DtY packed (c-frag layout), per-thread frags ----
    #pragma unroll
    for (int mt = 0; mt < 5; ++mt)
        #pragma unroll
        for (int nt = 0; nt < 2; ++nt) {
            int fragc = (wm * 5 + mt) * 8 + (wn * 2 + nt);
            *(float4*)(smem + DTY_OFF + (fragc * 32 + l) * 16) =
                make_float4(dty[(mt * 2 + nt) * 4 + 0], dty[(mt * 2 + nt) * 4 + 1],
                            dty[(mt * 2 + nt) * 4 + 2], dty[(mt * 2 + nt) * 4 + 3]);
        }
    // ---- zero y (fp32) ----
    for (int e = tid; e < PCOLS * YSTR; e += NTHREADS)
        *(float*)(smem + Y_OFF + e * 4) = 0.0f;

    float xold[40];
    #pragma unroll
    for (int v = 0; v < 40; ++v) xold[v] = 0.0f;
    __syncthreads();

    const float* Yp = (const float*)(smem + Y_OFF);

    // ---- main FISTA loop ----
    unsigned genl = 0;
    for (int it = 0; it < MAXIT; ++it) {
        // init acc with DtY
        float acc[10][4];
        #pragma unroll
        for (int mt = 0; mt < 5; ++mt)
            #pragma unroll
            for (int nt = 0; nt < 2; ++nt) {
                int fragc = (wm * 5 + mt) * 8 + (wn * 2 + nt);
                float4 c = *(const float4*)(smem + DTY_OFF + (fragc * 32 + l) * 16);
                acc[mt * 2 + nt][0] = c.x; acc[mt * 2 + nt][1] = c.y;
                acc[mt * 2 + nt][2] = c.z; acc[mt * 2 + nt][3] = c.w;
            }

        // GEMM: D[k,p] += A @ y  (3-chain split bf16)
        #pragma unroll 2
        for (int ks = 0; ks < 10; ++ks) {
            uint32_t bh[2][2], bl[2][2];
            #pragma unroll
            for (int nt = 0; nt < 2; ++nt) {
                const float* yrow = Yp + (wn * 16 + nt * 8 + g) * YSTR + ks * 16 + i4 * 2;
                float2 v0 = *(const float2*)(yrow);
                float2 v1 = *(const float2*)(yrow + 8);
                split_pack(v0.x, v0.y, bh[nt][0], bl[nt][0]);
                split_pack(v1.x, v1.y, bh[nt][1], bl[nt][1]);
            }
            #pragma unroll
            for (int mt = 0; mt < 5; ++mt) {
                int fi = ((wm * 5 + mt) * 10 + ks) * 32 + l;
                uint4 Ah = *(const uint4*)(smem + A_HI_OFF + fi * 16);
                uint4 Al = *(const uint4*)(smem + A_LO_OFF + fi * 16);
                uint32_t ah[4] = {Ah.x, Ah.y, Ah.z, Ah.w};
                uint32_t al[4] = {Al.x, Al.y, Al.z, Al.w};
                #pragma unroll
                for (int nt = 0; nt < 2; ++nt) {
                    mma_bf16(acc[mt * 2 + nt], ah, bh[nt]);
                    mma_bf16(acc[mt * 2 + nt], ah, bl[nt]);
                    mma_bf16(acc[mt * 2 + nt], al, bh[nt]);
                }
            }
        }

        const float tt = g_tts[it];
        const float onett = 1.0f + tt;
        float dsum = 0.0f;
        __syncthreads();   // all y reads complete before overwrite

        // epilogue: shrink + momentum + ||dx||^2 + write y fp32
        #pragma unroll
        for (int mt = 0; mt < 5; ++mt)
            #pragma unroll
            for (int nt = 0; nt < 2; ++nt)
                #pragma unroll
                for (int q = 0; q < 4; ++q) {
                    int ix = (mt * 2 + nt) * 4 + q;
                    float v  = acc[mt * 2 + nt][q];
                    float a  = fabsf(v) - lambd;
                    float xn = (a > 0.0f) ? copysignf(a, v) : 0.0f;
                    float xo = xold[ix];
                    float d  = xn - xo;
                    dsum = fmaf(d, d, dsum);
                    float yn = xn * onett - xo * tt;
                    xold[ix] = xn;
                    int row = wm * 80 + mt * 16 + g + ((q >> 1) << 3);
                    int col = wn * 16 + nt * 8 + i4 * 2 + (q & 1);
                    *(float*)(smem + Y_OFF + (col * YSTR + row) * 4) = yn;
                }

        // block reduce (fixed order -> deterministic)
        red[tid] = dsum;
        __syncthreads();
        if (tid == 0) {
            float s = 0.0f;
            for (int i = 0; i < NTHREADS; ++i) s += red[i];
            g_part[cta] = s;
        }
        __syncthreads();

        // software grid barrier
        if (tid == 0) {
            __threadfence();
            unsigned tk = atomicAdd(&g_count, 1);
            if (tk == (unsigned)(gridDim.x - 1)) {
                g_count = 0;
                __threadfence();
                atomicAdd(&g_gen, 1);
            } else {
                while (*((volatile unsigned*)&g_gen) == genl) { __nanosleep(64); }
            }
            __threadfence();
        }
        __syncthreads();
        genl++;

        // global convergence decision (identical in every CTA)
        if (tid < NCTA) red[tid] = *((volatile float*)(g_part + tid));
        __syncthreads();
        if (tid == 0) {
            float tot = 0.0f;
            for (int i = 0; i < NCTA; ++i) tot += red[i];
            float denom = (it == 0) ? (float)PDIM : (float)KDIM;
            *s_stop = (sqrtf(tot) < TOL_C * denom) ? 1 : 0;
        }
        __syncthreads();
        if (*s_stop) break;
    }

    // ---- output: out[(b*160 + row)*4096 + p0 + col] ----
    #pragma unroll
    for (int mt = 0; mt < 5; ++mt)
        #pragma unroll
        for (int nt = 0; nt < 2; ++nt)
            #pragma unroll
            for (int q = 0; q < 4; ++q) {
                int row = wm * 80 + mt * 16 + g + ((q >> 1) << 3);
                int col = wn * 16 + nt * 8 + i4 * 2 + (q & 1);
                out[((size_t)b * KDIM + row) * PDIM + p0 + col] =
                    xold[(mt * 2 + nt) * 4 + q];
            }
}

// ---------------- launch ----------------
extern "C" void kernel_launch(void* const* d_in, const int* in_sizes, int n_in,
                              void* d_out, int out_size) {
    const float* Drr    = (const float*)d_in[0];
    const float* Dtheta = (const float*)d_in[1];
    const float* x      = (const float*)d_in[2];
    float* out = (float*)d_out;

    cudaFuncSetAttribute(fista_kernel, cudaFuncAttributeMaxDynamicSharedMemorySize, SMEM_TOTAL);
    setup_kernel<<<1, 256>>>(Drr, Dtheta);
    fista_kernel<<<NCTA, NTHREADS, SMEM_TOTAL>>>(x, out);
}

// round 5
// speedup vs baseline: 4.9573x; 1.3199x over previous
#include <cuda_runtime.h>
#include <cuda_bf16.h>
#include <math.h>
#include <stdint.h>

// Problem constants
#define T_DIM   36
#define NPOLES  40
#define KDIM    160          // 4*N_POLES
#define PDIM    4096
#define PCOLS   64           // p columns per CTA
#define NCTA    128
#define NTHREADS 256         // 8 warps: 2 (m) x 4 (n)
#define MAXIT   100
#define LAM_C   0.1f
#define TOL_C   1e-4f

#define YSTR    164          // y fp32 row stride (floats)

// ---- dynamic smem layout (bytes) ----
#define RED_OFF   0          // 8 floats (per-warp partials)
#define STOP_OFF  64
#define A_HI_OFF  2048       // 100 frags * 32 lanes * 16B = 51200
#define A_LO_OFF  53248      // 51200
#define DTY_OFF   104448     // 80 c-frags * 32 * 16B = 40960
#define Y_OFF     145408     // 64 * 164 * 4 = 41984
#define SMEM_TOTAL 187392
// startup staging (consumed before overwrite):
#define DICT_STAGE Y_OFF     // dict [36][160] fp32 = 23040
#define X_STAGE    DTY_OFF   // x tile [36][64] fp32 = 9216

// ---------------- device globals ----------------
__device__ float    g_Dmat[T_DIM * KDIM];   // [t][k]
__device__ float    g_A[KDIM * KDIM];       // I - DtD/L  [k][j]
__device__ float    g_lambd;
__device__ float    g_linv;
__device__ float    g_tts[MAXIT];
__device__ float    g_part[NCTA];
__device__ unsigned g_count;
__device__ unsigned g_gen;                  // monotonic: # completed iterations

// ---------------- helpers ----------------
__device__ __forceinline__ void mma_bf16(float* c, const uint32_t* a, const uint32_t* b) {
    asm volatile(
        "mma.sync.aligned.m16n8k16.row.col.f32.bf16.bf16.f32 "
        "{%0,%1,%2,%3}, {%4,%5,%6,%7}, {%8,%9}, {%0,%1,%2,%3};"
        : "+f"(c[0]), "+f"(c[1]), "+f"(c[2]), "+f"(c[3])
        : "r"(a[0]), "r"(a[1]), "r"(a[2]), "r"(a[3]), "r"(b[0]), "r"(b[1]));
}
__device__ __forceinline__ void split_pack(float v0, float v1, uint32_t& hi, uint32_t& lo) {
    asm("cvt.rn.bf16x2.f32 %0, %1, %2;" : "=r"(hi) : "f"(v1), "f"(v0));
    float h0 = __uint_as_float(hi << 16);
    float h1 = __uint_as_float(hi & 0xffff0000u);
    asm("cvt.rn.bf16x2.f32 %0, %1, %2;" : "=r"(lo) : "f"(v1 - h1), "f"(v0 - h0));
}
// deterministic butterfly sum (identical instruction sequence everywhere)
__device__ __forceinline__ float warp_sum(float v) {
    v += __shfl_xor_sync(0xFFFFFFFFu, v, 16);
    v += __shfl_xor_sync(0xFFFFFFFFu, v, 8);
    v += __shfl_xor_sync(0xFFFFFFFFu, v, 4);
    v += __shfl_xor_sync(0xFFFFFFFFu, v, 2);
    v += __shfl_xor_sync(0xFFFFFFFFu, v, 1);
    return v;
}

// ---------------- setup ----------------
__global__ void setup_kernel(const float* __restrict__ Drr,
                             const float* __restrict__ Dtheta) {
    __shared__ float rbuf[256];
    __shared__ float s_linv;
    const int tid = threadIdx.x;

    if (tid < KDIM) {
        const int j = tid;
        const int g = j / NPOLES;
        const int n = j % NPOLES;
        const float rr = Drr[n];
        const float th = Dtheta[n];
        float vals[T_DIM];
        float pr = 1.0f, n2 = 0.0f;
        for (int i = 0; i < T_DIM; ++i) {
            float ang  = (float)i * th;
            float base = (g < 2) ? cosf(ang) : sinf(ang);
            float v = pr * base;
            if ((g & 1) && (i & 1)) v = -v;
            vals[i] = v; n2 += v * v; pr *= rr;
        }
        float G  = (n2 == 0.0f) ? 6.0f : sqrtf(n2);
        float gi = 1.0f / G;
        for (int i = 0; i < T_DIM; ++i) g_Dmat[i * KDIM + j] = vals[i] * gi;
    }
    __syncthreads();

    float sq = 0.0f;
    for (int e = tid; e < KDIM * KDIM; e += 256) {
        int i = e / KDIM, jj = e % KDIM;
        float s = 0.0f;
        for (int t = 0; t < T_DIM; ++t)
            s += g_Dmat[t * KDIM + i] * g_Dmat[t * KDIM + jj];
        g_A[e] = s;
        sq += s * s;
    }
    rbuf[tid] = sq;
    __syncthreads();
    if (tid == 0) {
        float tot = 0.0f;
        for (int i = 0; i < 256; ++i) tot += rbuf[i];
        float L = sqrtf(tot);
        s_linv  = 1.0f / L;
        g_linv  = s_linv;
        g_lambd = LAM_C * s_linv;
        double t = 1.0;
        for (int k = 0; k < MAXIT; ++k) {
            double tn = (1.0 + sqrt(1.0 + 4.0 * t * t)) * 0.5;
            g_tts[k] = (float)((t - 1.0) / tn);
            t = tn;
        }
        g_count = 0;
        g_gen   = 0;
    }
    __syncthreads();
    const float linv = s_linv;
    for (int e = tid; e < KDIM * KDIM; e += 256) {
        int i = e / KDIM, jj = e % KDIM;
        g_A[e] = ((i == jj) ? 1.0f : 0.0f) - g_A[e] * linv;
    }
    if (tid < NCTA) g_part[tid] = 0.0f;
}

// ---------------- persistent FISTA kernel (mma.sync bf16) ----------------
__global__ void __launch_bounds__(NTHREADS, 1)
fista_kernel(const float* __restrict__ x_in, float* __restrict__ out) {
    extern __shared__ __align__(16) char smem[];
    float* red    = (float*)(smem + RED_OFF);
    int*   s_stop = (int*)(smem + STOP_OFF);

    const int tid = threadIdx.x;
    const int wid = tid >> 5;
    const int l   = tid & 31;
    const int wm  = wid >> 2;          // 0..1  (80-row half)
    const int wn  = wid & 3;           // 0..3  (16-col stripe)
    const int g   = l >> 2;            // groupID
    const int i4  = l & 3;             // threadID_in_group
    const int cta = blockIdx.x;
    const int b   = cta >> 6;
    const int p0  = (cta & 63) * PCOLS;

    const float linv  = g_linv;
    const float lambd = g_lambd;

    // ---- stage dict [36][160] and x tile [36][64] fp32 ----
    for (int e = tid; e < T_DIM * KDIM; e += NTHREADS)
        *(float*)(smem + DICT_STAGE + e * 4) = g_Dmat[e];
    for (int e = tid; e < T_DIM * PCOLS; e += NTHREADS) {
        int t = e >> 6, pp = e & 63;
        *(float*)(smem + X_STAGE + e * 4) = x_in[(b * T_DIM + t) * PDIM + p0 + pp];
    }
    __syncthreads();

    // ---- DtY = linv * D^T x -> registers (c-frag order per thread) ----
    float dty[40];
    {
        #pragma unroll
        for (int v = 0; v < 40; ++v) dty[v] = 0.0f;
        const float* Ds = (const float*)(smem + DICT_STAGE);
        const float* Xs = (const float*)(smem + X_STAGE);
        for (int t = 0; t < T_DIM; ++t) {
            float dr[10], xc[4];
            #pragma unroll
            for (int mt = 0; mt < 5; ++mt) {
                dr[mt * 2]     = Ds[t * KDIM + wm * 80 + mt * 16 + g];
                dr[mt * 2 + 1] = Ds[t * KDIM + wm * 80 + mt * 16 + g + 8];
            }
            #pragma unroll
            for (int nt = 0; nt < 2; ++nt) {
                xc[nt * 2]     = Xs[t * PCOLS + wn * 16 + nt * 8 + i4 * 2];
                xc[nt * 2 + 1] = Xs[t * PCOLS + wn * 16 + nt * 8 + i4 * 2 + 1];
            }
            #pragma unroll
            for (int mt = 0; mt < 5; ++mt)
                #pragma unroll
                for (int nt = 0; nt < 2; ++nt)
                    #pragma unroll
                    for (int q = 0; q < 4; ++q)
                        dty[(mt * 2 + nt) * 4 + q] =
                            fmaf(dr[mt * 2 + (q >> 1)], xc[nt * 2 + (q & 1)],
                                 dty[(mt * 2 + nt) * 4 + q]);
        }
        #pragma unroll
        for (int v = 0; v < 40; ++v) dty[v] *= linv;
    }
    __syncthreads();   // dict/x staging consumed

    // ---- pack A into fragment-native bf16 hi/lo layout ----
    for (int e = tid; e < 100 * 32 * 4; e += NTHREADS) {
        int frag = e >> 7;
        int lane = (e >> 2) & 31;
        int reg  = e & 3;
        int mt   = frag / 10, ks = frag % 10;
        int r = mt * 16 + (lane >> 2) + ((reg & 1) ? 8 : 0);
        int k = ks * 16 + (lane & 3) * 2 + ((reg & 2) ? 8 : 0);
        float v0 = g_A[r * KDIM + k];
        float v1 = g_A[r * KDIM + k + 1];
        uint32_t hi, lo;
        split_pack(v0, v1, hi, lo);
        *(uint32_t*)(smem + A_HI_OFF + e * 4) = hi;
        *(uint32_t*)(smem + A_LO_OFF + e * 4) = lo;
    }
    // ---- store DtY packed (c-frag layout) ----
    #pragma unroll
    for (int mt = 0; mt < 5; ++mt)
        #pragma unroll
        for (int nt = 0; nt < 2; ++nt) {
            int fragc = (wm * 5 + mt) * 8 + (wn * 2 + nt);
            *(float4*)(smem + DTY_OFF + (fragc * 32 + l) * 16) =
                make_float4(dty[(mt * 2 + nt) * 4 + 0], dty[(mt * 2 + nt) * 4 + 1],
                            dty[(mt * 2 + nt) * 4 + 2], dty[(mt * 2 + nt) * 4 + 3]);
        }
    // ---- zero y (fp32) ----
    for (int e = tid; e < PCOLS * YSTR; e += NTHREADS)
        *(float*)(smem + Y_OFF + e * 4) = 0.0f;

    float xold[40];
    #pragma unroll
    for (int v = 0; v < 40; ++v) xold[v] = 0.0f;
    __syncthreads();

    const float* Yp = (const float*)(smem + Y_OFF);

    // ---- main FISTA loop (barrier hidden behind next GEMM) ----
    for (int it = 0; it < MAXIT; ++it) {
        // init acc with DtY
        float acc[10][4];
        #pragma unroll
        for (int mt = 0; mt < 5; ++mt)
            #pragma unroll
            for (int nt = 0; nt < 2; ++nt) {
                int fragc = (wm * 5 + mt) * 8 + (wn * 2 + nt);
                float4 c = *(const float4*)(smem + DTY_OFF + (fragc * 32 + l) * 16);
                acc[mt * 2 + nt][0] = c.x; acc[mt * 2 + nt][1] = c.y;
                acc[mt * 2 + nt][2] = c.z; acc[mt * 2 + nt][3] = c.w;
            }

        // GEMM: D[k,p] += A @ y (3-chain split bf16); chains interleaved across
        // (mt,nt) so back-to-back mmas hit distinct accumulators.
        #pragma unroll 2
        for (int ks = 0; ks < 10; ++ks) {
            uint32_t bh[2][2], bl[2][2];
            #pragma unroll
            for (int nt = 0; nt < 2; ++nt) {
                const float* yrow = Yp + (wn * 16 + nt * 8 + g) * YSTR + ks * 16 + i4 * 2;
                float2 v0 = *(const float2*)(yrow);
                float2 v1 = *(const float2*)(yrow + 8);
                split_pack(v0.x, v0.y, bh[nt][0], bl[nt][0]);
                split_pack(v1.x, v1.y, bh[nt][1], bl[nt][1]);
            }
            uint32_t ah[5][4], al[5][4];
            #pragma unroll
            for (int mt = 0; mt < 5; ++mt) {
                int fi = ((wm * 5 + mt) * 10 + ks) * 32 + l;
                uint4 Ah = *(const uint4*)(smem + A_HI_OFF + fi * 16);
                uint4 Al = *(const uint4*)(smem + A_LO_OFF + fi * 16);
                ah[mt][0] = Ah.x; ah[mt][1] = Ah.y; ah[mt][2] = Ah.z; ah[mt][3] = Ah.w;
                al[mt][0] = Al.x; al[mt][1] = Al.y; al[mt][2] = Al.z; al[mt][3] = Al.w;
            }
            #pragma unroll
            for (int mt = 0; mt < 5; ++mt)
                #pragma unroll
                for (int nt = 0; nt < 2; ++nt)
                    mma_bf16(acc[mt * 2 + nt], ah[mt], bh[nt]);
            #pragma unroll
            for (int mt = 0; mt < 5; ++mt)
                #pragma unroll
                for (int nt = 0; nt < 2; ++nt)
                    mma_bf16(acc[mt * 2 + nt], ah[mt], bl[nt]);
            #pragma unroll
            for (int mt = 0; mt < 5; ++mt)
                #pragma unroll
                for (int nt = 0; nt < 2; ++nt)
                    mma_bf16(acc[mt * 2 + nt], al[mt], bh[nt]);
        }

        // ---- resolve stop decision for iteration it-1 (overlapped) ----
        if (it > 0) {
            if (tid == 0) {
                while (*((volatile unsigned*)&g_gen) < (unsigned)it) { __nanosleep(32); }
            }
        }
        __syncthreads();   // joins poll; all warps done reading y
        if (it > 0) {
            if (wid == 0) {
                // fixed-order deterministic sum of 128 partials
                float s = *((volatile float*)(g_part + l));
                s += *((volatile float*)(g_part + l + 32));
                s += *((volatile float*)(g_part + l + 64));
                s += *((volatile float*)(g_part + l + 96));
                float tot = warp_sum(s);
                if (l == 0) {
                    float denom = (it == 1) ? (float)PDIM : (float)KDIM;
                    *s_stop = (sqrtf(tot) < TOL_C * denom) ? 1 : 0;
                }
            }
            __syncthreads();
            if (*s_stop) break;   // xold holds x_it (frozen), matches reference
        }

        const float tt = g_tts[it];
        const float onett = 1.0f + tt;
        float dsum = 0.0f;

        // epilogue: shrink + momentum + ||dx||^2 + write y fp32
        #pragma unroll
        for (int mt = 0; mt < 5; ++mt)
            #pragma unroll
            for (int nt = 0; nt < 2; ++nt)
                #pragma unroll
                for (int q = 0; q < 4; ++q) {
                    int ix = (mt * 2 + nt) * 4 + q;
                    float v  = acc[mt * 2 + nt][q];
                    float a  = fabsf(v) - lambd;
                    float xn = (a > 0.0f) ? copysignf(a, v) : 0.0f;
                    float xo = xold[ix];
                    float d  = xn - xo;
                    dsum = fmaf(d, d, dsum);
                    float yn = xn * onett - xo * tt;
                    xold[ix] = xn;
                    int row = wm * 80 + mt * 16 + g + ((q >> 1) << 3);
                    int col = wn * 16 + nt * 8 + i4 * 2 + (q & 1);
                    *(float*)(smem + Y_OFF + (col * YSTR + row) * 4) = yn;
                }

        // deterministic block reduce: warp butterfly + 8-way serial (fixed order)
        float ws = warp_sum(dsum);
        if (l == 0) red[wid] = ws;
        __syncthreads();   // also: y writes visible before next GEMM
        if (tid == 0) {
            float s = red[0];
            #pragma unroll
            for (int i = 1; i < 8; ++i) s += red[i];
            g_part[cta] = s;
            __threadfence();
            unsigned tk = atomicAdd(&g_count, 1);
            if (tk == (unsigned)(NCTA - 1)) {
                g_count = 0;
                __threadfence();
                atomicAdd(&g_gen, 1);   // completed iteration count
            }
        }
        // NO wait here — next GEMM starts immediately; decision deferred.
    }

    // ---- output: out[(b*160 + row)*4096 + p0 + col] ----
    #pragma unroll
    for (int mt = 0; mt < 5; ++mt)
        #pragma unroll
        for (int nt = 0; nt < 2; ++nt)
            #pragma unroll
            for (int q = 0; q < 4; ++q) {
                int row = wm * 80 + mt * 16 + g + ((q >> 1) << 3);
                int col = wn * 16 + nt * 8 + i4 * 2 + (q & 1);
                out[((size_t)b * KDIM + row) * PDIM + p0 + col] =
                    xold[(mt * 2 + nt) * 4 + q];
            }
}

// ---------------- launch ----------------
extern "C" void kernel_launch(void* const* d_in, const int* in_sizes, int n_in,
                              void* d_out, int out_size) {
    const float* Drr    = (const float*)d_in[0];
    const float* Dtheta = (const float*)d_in[1];
    const float* x      = (const float*)d_in[2];
    float* out = (float*)d_out;

    cudaFuncSetAttribute(fista_kernel, cudaFuncAttributeMaxDynamicSharedMemorySize, SMEM_TOTAL);
    setup_kernel<<<1, 256>>>(Drr, Dtheta);
    fista_kernel<<<NCTA, NTHREADS, SMEM_TOTAL>>>(x, out);
}